// round 15
// baseline (speedup 1.0000x reference)
#include <cuda_runtime.h>
#include <cstdint>

// ---------------------------------------------------------------------------
// Layer-pipelined cluster LSTM with TWO-CHAIN INTERLEAVE.
// 4 clusters x 8 CTAs; each cluster runs TWO batch chains (weights shared in
// registers, only state duplicated). Ranks 0-3 layer1, ranks 4-7 layer2; each
// CTA owns 32 units. While chain A's DSMEM h-push is in flight, the warps run
// chain B's full step -> exposed exchange latency is hidden by real work.
// FC is DISTRIBUTED (each L1 rank owns 32 Wfc rows, pushes its forecast slice
// to all L1 ranks' replay buffers + F counter) to fit 2 replay buffers in
// SMEM. Per-chain sync = R14's proven scheme (aggregated red.add.release
// counters, single ld.acquire.u64 polls, split bar.arrive/bar.sync over 4
// rotating ids per chain, depth-4 h ring, quad-buffered partials).
// ---------------------------------------------------------------------------

#define H    128
#define NTH  256
#define TENC 168
#define FLEN 168

typedef unsigned long long u64;

// SMEM float offsets
#define OFF_BUF0 0                        // chain0 replay buffer / X: 169*128
#define OFF_BUF1 (169*128)                // chain1 replay buffer   (21632)
#define OFF_WFC  (2*169*128)              // own 32 Wfc rows, stride 129
#define OFF_BFC  (OFF_WFC + 32*129)       // own 32 bfc values
#define OFF_HB0  (OFF_BFC + 32)           // chain0 h ring: 8 slots x 128
#define OFF_HB1  (OFF_HB0 + 1024)         // chain1 h ring
#define OFF_P0   (OFF_HB1 + 1024)         // chain0 partials, quad: 4*256
#define OFF_P1   (OFF_P0 + 1024)          // chain1 partials
#define OFF_HS0  (OFF_P1 + 1024)          // chain0 h stage: 32
#define OFF_HS1  (OFF_HS0 + 32)           // chain1 h stage: 32
#define OFF_SQ   (OFF_HS1 + 32)           // 16 u32: chain c @ +8c: A0,A1,B0,B1,F
#define SMEM_FLOATS (OFF_SQ + 16)
#define SMEM_BYTES  (SMEM_FLOATS * 4)     // 206,400 B

static __device__ __forceinline__ float fast_ex2(float x)
{ float r; asm("ex2.approx.f32 %0,%1;" : "=f"(r) : "f"(x)); return r; }
static __device__ __forceinline__ float fast_rcp(float x)
{ float r; asm("rcp.approx.f32 %0,%1;" : "=f"(r) : "f"(x)); return r; }
static __device__ __forceinline__ float sigf(float x)
{ return fast_rcp(1.0f + fast_ex2(-1.44269504f * x)); }
static __device__ __forceinline__ float tanh_fast(float x)
{ return fmaf(2.0f, sigf(2.0f * x), -1.0f); }

static __device__ __forceinline__ uint32_t s2u(const void *p)
{
    uint32_t a;
    asm("{ .reg .u64 t; cvta.to.shared.u64 t, %1; cvt.u32.u64 %0, t; }"
        : "=r"(a) : "l"(p));
    return a;
}
static __device__ __forceinline__ uint32_t mapa32(uint32_t a, uint32_t r)
{
    uint32_t d;
    asm("mapa.shared::cluster.u32 %0, %1, %2;" : "=r"(d) : "r"(a), "r"(r));
    return d;
}
static __device__ __forceinline__ void stc4(uint32_t a, float4 v)
{
    asm volatile("st.shared::cluster.v4.f32 [%0], {%1,%2,%3,%4};"
                 :: "r"(a), "f"(v.x), "f"(v.y), "f"(v.z), "f"(v.w) : "memory");
}
static __device__ __forceinline__ void red_add_rel(uint32_t a)
{
    asm volatile("red.release.cluster.shared::cluster.add.u32 [%0], %1;"
                 :: "r"(a), "r"(1u) : "memory");
}
static __device__ __forceinline__ u64 ldacq64(uint32_t a)
{
    u64 v;
    asm volatile("ld.acquire.cluster.shared::cta.u64 %0, [%1];"
                 : "=l"(v) : "r"(a) : "memory");
    return v;
}
static __device__ __forceinline__ uint32_t ldacq32(uint32_t a)
{
    uint32_t v;
    asm volatile("ld.acquire.cluster.shared::cta.u32 %0, [%1];"
                 : "=r"(v) : "r"(a) : "memory");
    return v;
}
// Wait until BOTH u32 counters in the pair at addr reach >= n4.
static __device__ __forceinline__ void waitc(uint32_t addr, int n4)
{
    if (n4 <= 0) return;
    const uint32_t un = (uint32_t)n4;
    for (;;) {
        u64 v = ldacq64(addr);
        uint32_t m = min((uint32_t)v, (uint32_t)(v >> 32));
        if (m >= un) break;
    }
}
static __device__ __forceinline__ void waitc32(uint32_t addr, int n)
{
    if (n <= 0) return;
    while (ldacq32(addr) < (uint32_t)n) { }
}

static __device__ __forceinline__ void bar_arrive(uint32_t id)
{ asm volatile("bar.arrive %0, %1;" :: "r"(id), "r"(256u) : "memory"); }
static __device__ __forceinline__ void bar_sync(uint32_t id)
{ asm volatile("bar.sync %0, %1;" :: "r"(id), "r"(256u) : "memory"); }

static __device__ __forceinline__ void fma2(u64 &acc, u64 a, u64 b)
{ asm("fma.rn.f32x2 %0, %1, %2, %0;" : "+l"(acc) : "l"(a), "l"(b)); }
static __device__ __forceinline__ float2 up2(u64 a)
{ float2 r; asm("mov.b64 {%0,%1}, %2;" : "=f"(r.x), "=f"(r.y) : "l"(a)); return r; }

// 128-term dot; all lanes read the SAME addresses (pure broadcast).
static __device__ __forceinline__ float dot128b(const u64 *__restrict__ w,
                                                uint32_t base)
{
    u64 a0 = 0, a1 = 0, a2 = 0, a3 = 0;
#pragma unroll
    for (int q = 0; q < 16; q++) {
        uint32_t ad = base + (uint32_t)(q << 5);
        u64 x0, x1, x2, x3;
        asm volatile("ld.shared.v2.u64 {%0,%1},[%2];" : "=l"(x0), "=l"(x1) : "r"(ad));
        asm volatile("ld.shared.v2.u64 {%0,%1},[%2];" : "=l"(x2), "=l"(x3) : "r"(ad + 16));
        fma2(a0, w[4 * q + 0], x0);
        fma2(a1, w[4 * q + 1], x1);
        fma2(a2, w[4 * q + 2], x2);
        fma2(a3, w[4 * q + 3], x3);
    }
    float2 f0 = up2(a0), f1 = up2(a1), f2 = up2(a2), f3 = up2(a3);
    return ((f0.x + f0.y) + (f1.x + f1.y)) + ((f2.x + f2.y) + (f3.x + f3.y));
}

__global__ void __launch_bounds__(NTH, 1) wfm_kernel(
    const float *__restrict__ X,   const float *__restrict__ Wih,
    const float *__restrict__ Whh, const float *__restrict__ bih,
    const float *__restrict__ bhh, const float *__restrict__ Wfc,
    const float *__restrict__ bfc, float *__restrict__ OUT)
{
    extern __shared__ float sm[];
    const int tid  = threadIdx.x;
    const int grp0 = blockIdx.x >> 3;      // cluster id 0..3 -> batches 2g,2g+1
    const int cl   = blockIdx.x & 7;
    const int wrp  = tid >> 5;
    const int lane = tid & 31;
    const int role = cl >> 2;              // 0: layer-1 CTA, 1: layer-2 CTA
    const int base = (cl & 3) * 32;        // owned unit base within H
    const int p    = wrp >> 2;             // 0: early group, 1: critical group
    const int rloc = ((wrp & 3) << 5) + lane;   // local gate row 0..127
    const int b0   = grp0 * 2;

    // ---- weights -> registers (shared by both chains): role-aware pick ----
    u64 w[64];
    {
        const int g = rloc >> 5, uu = rloc & 31;
        const int R = role * 512 + g * H + base + uu;
        const bool useIh = (role == 0) ? (p == 0) : (p == 1);
        const float *src = useIh ? &Wih[R * H] : &Whh[R * H];
        const u64 *ps = (const u64 *)src;
#pragma unroll
        for (int i = 0; i < 64; i++) w[i] = __ldg(ps + i);
    }
    const int cu = ((wrp & 1) << 4) + (lane & 15);
    float bi[4];
#pragma unroll
    for (int g2 = 0; g2 < 4; g2++) {
        int R = role * 512 + g2 * H + base + cu;
        bi[g2] = __ldg(&bih[R]) + __ldg(&bhh[R]);
    }

    // ---- SMEM staging: X for both chains, own Wfc/bfc slice, zero state ----
    for (int i = tid; i < TENC * H; i += NTH) {
        sm[OFF_BUF0 + i] = __ldg(&X[(b0 + 0) * TENC * H + i]);
        sm[OFF_BUF1 + i] = __ldg(&X[(b0 + 1) * TENC * H + i]);
    }
    for (int i = tid; i < 32 * H; i += NTH) {
        int r = i >> 7, c = i & 127;
        sm[OFF_WFC + r * 129 + c] = __ldg(&Wfc[((cl & 3) * 32 + r) * H + c]);
    }
    if (tid < 32) sm[OFF_BFC + tid] = __ldg(&bfc[(cl & 3) * 32 + tid]);
    for (int i = tid; i < SMEM_FLOATS - OFF_HB0; i += NTH)
        sm[OFF_HB0 + i] = 0.f;            // rings, partials, stages, counters

    const uint32_t sbase = s2u(sm);
    const uint32_t SQ0   = sbase + OFF_SQ * 4;
    __syncthreads();
    asm volatile("barrier.cluster.arrive.aligned;" ::: "memory");
    asm volatile("barrier.cluster.wait.aligned;"   ::: "memory");

    // remote base for rank=lane (valid: warps 0,1, lane<8)
    uint32_t br = 0;
    if (wrp < 2 && lane < 8) br = mapa32(sbase, (uint32_t)lane);

    float ccA = 0.f, ccB = 0.f;            // c-state per chain (warps 0,1)

    // ---- combine + push for chain c ----
    auto combine_push = [&](int c, float &cc, int s, int hbslot, int rec) {
        const float *pp = &sm[(c ? OFF_P1 : OFF_P0) + (s & 3) * 256];
        const int HSc = c ? OFF_HS1 : OFF_HS0;
        if (lane < 16) {
            float2 q0 = *(const float2 *)&pp[0 * 64 + cu * 2];
            float2 q1 = *(const float2 *)&pp[1 * 64 + cu * 2];
            float2 q2 = *(const float2 *)&pp[2 * 64 + cu * 2];
            float2 q3 = *(const float2 *)&pp[3 * 64 + cu * 2];
            float gi = q0.x + q0.y + bi[0];
            float gf = q1.x + q1.y + bi[1];
            float gg = q2.x + q2.y + bi[2];
            float go = q3.x + q3.y + bi[3];
            cc = sigf(gf) * cc + sigf(gi) * tanh_fast(gg);
            sm[HSc + cu] = sigf(go) * tanh_fast(cc);
        }
        __syncwarp();
        if (lane < 8) {
            const float4 *hs = (const float4 *)&sm[HSc + ((wrp & 1) << 4)];
            float4 h0 = hs[0], h1 = hs[1], h2 = hs[2], h3 = hs[3];
            uint32_t d = br + (uint32_t)(c ? OFF_HB1 : OFF_HB0) * 4
                       + (uint32_t)(base + ((wrp & 1) << 4)) * 4
                       + (uint32_t)hbslot * 512;
            stc4(d, h0); stc4(d + 16, h1); stc4(d + 32, h2); stc4(d + 48, h3);
            if (rec >= 0 && lane < 4) {
                uint32_t bd = br + (uint32_t)(c ? OFF_BUF1 : OFF_BUF0) * 4
                            + (uint32_t)(base + ((wrp & 1) << 4)) * 4
                            + (uint32_t)rec * 512;
                stc4(bd, h0); stc4(bd + 16, h1); stc4(bd + 32, h2); stc4(bd + 48, h3);
            }
            red_add_rel(br + (uint32_t)OFF_SQ * 4 + (uint32_t)c * 32
                        + (uint32_t)(role * 2 + (wrp & 1)) * 4);
        }
    };

    auto stepL1 = [&](int c, float &cc, int s, int t, int bneed, int fneed) {
        const uint32_t SQc = SQ0 + (uint32_t)c * 32;
        float v;
        if (p == 0) {                          // early: x/replay dot
            if (fneed > 0) waitc32(SQc + 16, fneed);  // FC fill of row t==k
            int gate = s - 3;                  // WAR on h1 ring slot s&3
            if (bneed > gate) gate = bneed;    // replay-row freshness
            waitc(SQc + 8, 4 * gate);
            v = dot128b(w, sbase + (uint32_t)((c ? OFF_BUF1 : OFF_BUF0) + t * 128) * 4);
        } else {                               // critical: h1(s-1)
            waitc(SQc, 4 * s);
            v = dot128b(w, sbase + (uint32_t)((c ? OFF_HB1 : OFF_HB0) + ((s - 1) & 3) * 128) * 4);
        }
        uint32_t sa = sbase + (uint32_t)((c ? OFF_P1 : OFF_P0) + (s & 3) * 256 + rloc * 2 + p) * 4;
        asm volatile("st.shared.f32 [%0],%1;" :: "r"(sa), "f"(v) : "memory");
        uint32_t bid = 1 + (uint32_t)c * 4 + (s & 3);
        if (wrp < 2) { bar_sync(bid); combine_push(c, cc, s, s & 3, -1); }
        else          bar_arrive(bid);
    };

    auto stepL2 = [&](int c, float &cc, int s, int rec) {
        const uint32_t SQc = SQ0 + (uint32_t)c * 32;
        float v;
        if (p == 0) {                          // early: h2(s-1) recurrent
            waitc(SQc + 8, 4 * s);
            v = dot128b(w, sbase + (uint32_t)((c ? OFF_HB1 : OFF_HB0) + (4 + ((s - 1) & 3)) * 128) * 4);
        } else {                               // critical: fresh h1(s)
            waitc(SQc, 4 * (s + 1));
            v = dot128b(w, sbase + (uint32_t)((c ? OFF_HB1 : OFF_HB0) + (s & 3) * 128) * 4);
        }
        uint32_t sa = sbase + (uint32_t)((c ? OFF_P1 : OFF_P0) + (s & 3) * 256 + rloc * 2 + p) * 4;
        asm volatile("st.shared.f32 [%0],%1;" :: "r"(sa), "f"(v) : "memory");
        uint32_t bid = 1 + (uint32_t)c * 4 + (s & 3);
        if (wrp < 2) { bar_sync(bid); combine_push(c, cc, s, 4 + (s & 3), rec); }
        else          bar_arrive(bid);
    };

    // Distributed FC: this L1 rank computes its 32 forecast rows, pushes them
    // into row k+1 of all 4 L1 ranks' replay buffers, bumps F counter.
    auto fc = [&](int c, int k, int s) {
        const uint32_t SQc = SQ0 + (uint32_t)c * 32;
        if (wrp < 2) {
            waitc(SQc + 8, 4 * s);             // final h2 of iteration landed
            const float *hv = &sm[(c ? OFF_HB1 : OFF_HB0) + (4 + ((s - 1) & 3)) * 128];
            int row = tid >> 1, p2 = tid & 1;  // rows 0..31 of own slice
            const float *wr = &sm[OFF_WFC + row * 129 + p2 * 64];
            const float *hq = hv + p2 * 64;
            float a = 0.f;
#pragma unroll
            for (int j = 0; j < 64; j++) a = fmaf(wr[j], hq[j], a);
            a += __shfl_xor_sync(0xffffffffu, a, 1);
            if (p2 == 0) {
                float val = a + sm[OFF_BFC + row];
                sm[(c ? OFF_HS1 : OFF_HS0) + row] = val;
                OUT[((uint32_t)(b0 + c) * FLEN + k) * H + (cl & 3) * 32 + row] = val;
            }
        }
        __syncthreads();
        if (wrp == 0 && lane < 4) {
            uint32_t dst = br + (uint32_t)(c ? OFF_BUF1 : OFF_BUF0) * 4
                         + (uint32_t)((k + 1) * 128 + (cl & 3) * 32) * 4;
            const float4 *h4 = (const float4 *)&sm[c ? OFF_HS1 : OFF_HS0];
#pragma unroll
            for (int i = 0; i < 8; i++) stc4(dst + (uint32_t)i * 16, h4[i]);
            red_add_rel(br + (uint32_t)OFF_SQ * 4 + (uint32_t)c * 32 + 16);
        }
    };

    int s = 0;
    if (role == 0) {
        // ---------------- layer-1 pipeline stage ----------------
        for (int t = 0; t < TENC; t++) {
            stepL1(0, ccA, s, t, 0, 0);
            stepL1(1, ccB, s, t, 0, 0);
            s++;
        }
        for (int k = 0; k < FLEN; k++) {
            for (int t = 0; t <= k; t++) {
                int bneed = (t < k) ? (s - k + 1) : (k == 0 ? s : 0);
                int fneed = (t == k && k > 0) ? 4 * k : 0;
                stepL1(0, ccA, s, t, bneed, fneed);
                stepL1(1, ccB, s, t, bneed, fneed);
                s++;
            }
            fc(0, k, s);
            fc(1, k, s);
        }
    } else {
        // ---------------- layer-2 pipeline stage ----------------
        for (int t = 0; t < TENC; t++) {
            int rec = (t == TENC - 1) ? 0 : -1;
            stepL2(0, ccA, s, rec);
            stepL2(1, ccB, s, rec);
            s++;
        }
        for (int k = 0; k < FLEN; k++)
            for (int t = 0; t <= k; t++) {
                stepL2(0, ccA, s, t);
                stepL2(1, ccB, s, t);
                s++;
            }
    }

    asm volatile("barrier.cluster.arrive.aligned;" ::: "memory");
    asm volatile("barrier.cluster.wait.aligned;"   ::: "memory");
}

extern "C" void kernel_launch(void *const *d_in, const int *in_sizes, int n_in,
                              void *d_out, int out_size)
{
    const float *X   = (const float *)d_in[0];
    const float *Wih = (const float *)d_in[1];
    const float *Whh = (const float *)d_in[2];
    const float *bih = (const float *)d_in[3];
    const float *bhh = (const float *)d_in[4];
    const float *Wfc = (const float *)d_in[5];
    const float *bfc = (const float *)d_in[6];
    float *OUT = (float *)d_out;

    cudaFuncSetAttribute(wfm_kernel,
                         cudaFuncAttributeMaxDynamicSharedMemorySize,
                         SMEM_BYTES);

    cudaLaunchConfig_t cfg = {};
    cfg.gridDim  = {32, 1, 1};
    cfg.blockDim = {NTH, 1, 1};
    cfg.dynamicSmemBytes = SMEM_BYTES;
    cudaLaunchAttribute attrs[1];
    attrs[0].id = cudaLaunchAttributeClusterDimension;
    attrs[0].val.clusterDim = {8, 1, 1};
    cfg.attrs = attrs;
    cfg.numAttrs = 1;

    cudaLaunchKernelEx(&cfg, wfm_kernel, X, Wih, Whh, bih, bhh, Wfc, bfc, OUT);
}